// round 1
// baseline (speedup 1.0000x reference)
#include <cuda_runtime.h>
#include <cstdint>

// Problem constants
#define TOK   16384
#define DIM   2048
#define NE    16
#define BT    128      // tokens per CTA
#define BD    64       // d-chunk per pipeline stage
#define NTHR  256
#define NCHUNK (DIM / BD)   // 32

// smem layout (float4 units):
//   x stage0: [0,    2048)   -> 128 tokens x 16 dvec
//   x stage1: [2048, 4096)
//   w stage0: [4096, 4352)   -> 16 experts x 16 dvec (transposed, K-major per expert)
//   w stage1: [4352, 4608)
#define SMEM_F4_TOTAL 4608   // 73728 bytes

__device__ __forceinline__ uint32_t smem_u32(const void* p) {
    uint32_t a;
    asm("{ .reg .u64 t; cvta.to.shared.u64 t, %1; cvt.u32.u64 %0, t; }" : "=r"(a) : "l"(p));
    return a;
}

#define CP_ASYNC16(smem_addr, gptr) \
    asm volatile("cp.async.cg.shared.global [%0], [%1], 16;" :: "r"(smem_addr), "l"(gptr))
#define CP_COMMIT() asm volatile("cp.async.commit_group;" ::: "memory")
#define CP_WAIT1()  asm volatile("cp.async.wait_group 1;" ::: "memory")
#define CP_WAIT0()  asm volatile("cp.async.wait_group 0;" ::: "memory")

#define FMA2(c, a, b) \
    asm("fma.rn.f32x2 %0, %1, %2, %0;" : "+l"(c) : "l"(a), "l"(b))

__global__ void __launch_bounds__(NTHR, 1)
gating_moe_kernel(const float* __restrict__ x,
                  const float* __restrict__ noise,
                  const float* __restrict__ W,
                  const float* __restrict__ b,
                  float* __restrict__ out)
{
    extern __shared__ float4 smem[];
    const int tid  = threadIdx.x;
    const int dp   = tid & 7;          // d-partition (0..7)
    const int slot = tid >> 3;         // 0..31
    const int tg   = slot & 15;        // token group (8 tokens each)
    const int eg   = slot >> 4;        // expert group (0/1, 8 experts each)
    const int tok0 = blockIdx.x * BT;

    const uint32_t sb = smem_u32(smem);

    // ---- prefetch helper (inlined twice below) ----
    // x chunk: 2048 float4 -> 8 per thread ; W chunk: 256 float4 -> 1 per thread
    auto prefetch = [&](int c, int stage) {
        const uint32_t xbase = sb + stage * 2048 * 16;
        const uint32_t wbase = sb + (4096 + stage * 256) * 16;
        #pragma unroll
        for (int k = 0; k < 8; k++) {
            int idx = tid + NTHR * k;
            int t  = idx >> 4;
            int dv = idx & 15;
            const float* g = x + (size_t)(tok0 + t) * DIM + c * BD + dv * 4;
            CP_ASYNC16(xbase + (uint32_t)(t * 16 + dv) * 16u, g);
        }
        {
            int e  = tid >> 4;
            int dv = tid & 15;
            const float* g = W + (size_t)e * DIM + c * BD + dv * 4;
            CP_ASYNC16(wbase + (uint32_t)(e * 16 + dv) * 16u, g);
        }
    };

    // ---- accumulators: 8 tokens x 8 experts, each a packed f32x2 over (d even, d odd) ----
    unsigned long long acc[8][8];
    #pragma unroll
    for (int t = 0; t < 8; t++)
        #pragma unroll
        for (int e = 0; e < 8; e++) acc[t][e] = 0ULL;

    prefetch(0, 0);
    CP_COMMIT();

    for (int c = 0; c < NCHUNK; c++) {
        const int stage = c & 1;
        if (c + 1 < NCHUNK) {
            prefetch(c + 1, (c + 1) & 1);
            CP_COMMIT();
            CP_WAIT1();
        } else {
            CP_WAIT0();
        }
        __syncthreads();

        const ulonglong2* xs = (const ulonglong2*)(smem + stage * 2048);
        const ulonglong2* ws = (const ulonglong2*)(smem + 4096 + stage * 256);

        #pragma unroll
        for (int j4 = 0; j4 < 2; j4++) {
            const int sl = dp + 8 * j4;     // dvec slot: conflict-free mod 8
            ulonglong2 xv[8];
            #pragma unroll
            for (int t = 0; t < 8; t++)
                xv[t] = xs[(tg * 8 + t) * 16 + sl];
            #pragma unroll
            for (int e = 0; e < 8; e++) {
                ulonglong2 wv = ws[(eg * 8 + e) * 16 + sl];
                #pragma unroll
                for (int t = 0; t < 8; t++) {
                    FMA2(acc[t][e], xv[t].x, wv.x);
                    FMA2(acc[t][e], xv[t].y, wv.y);
                }
            }
        }
        __syncthreads();
    }

    // ---- reduce f32x2 halves + cross-dp butterfly (dp lives in lane bits 0..2) ----
    float lg[8][8];
    #pragma unroll
    for (int t = 0; t < 8; t++) {
        #pragma unroll
        for (int e = 0; e < 8; e++) {
            unsigned int lo = (unsigned int)(acc[t][e] & 0xffffffffULL);
            unsigned int hi = (unsigned int)(acc[t][e] >> 32);
            float s = __uint_as_float(lo) + __uint_as_float(hi);
            s += __shfl_xor_sync(0xffffffffu, s, 1);
            s += __shfl_xor_sync(0xffffffffu, s, 2);
            s += __shfl_xor_sync(0xffffffffu, s, 4);
            lg[t][e] = s;
        }
    }

    float* Ls = (float*)smem;   // logits [128][16], reuse pipeline smem
    if (dp == 0) {
        #pragma unroll
        for (int t = 0; t < 8; t++)
            #pragma unroll
            for (int e = 0; e < 8; e++)
                Ls[(tg * 8 + t) * 16 + (eg * 8 + e)] = lg[t][e];
    }
    __syncthreads();

    // ---- epilogue: one token per thread (threads 0..127) ----
    if (tid < BT) {
        const int gtok = tok0 + tid;
        const float4* nz = (const float4*)(noise + (size_t)gtok * NE);
        float4 n0 = nz[0], n1 = nz[1], n2 = nz[2], n3 = nz[3];
        const float4* bb4 = (const float4*)b;
        float4 b0 = bb4[0], b1 = bb4[1], b2 = bb4[2], b3 = bb4[3];

        float nn[16] = {n0.x, n0.y, n0.z, n0.w, n1.x, n1.y, n1.z, n1.w,
                        n2.x, n2.y, n2.z, n2.w, n3.x, n3.y, n3.z, n3.w};
        float bv[16] = {b0.x, b0.y, b0.z, b0.w, b1.x, b1.y, b1.z, b1.w,
                        b2.x, b2.y, b2.z, b2.w, b3.x, b3.y, b3.z, b3.w};

        float v[16];
        #pragma unroll
        for (int e = 0; e < 16; e++) {
            float l = Ls[tid * 16 + e] + bv[e];
            v[e] = l + 0.1f * nn[e];
        }

        // top-2 (stable: ties keep earlier index first, matching jax top_k)
        float v1 = -1e30f, v2 = -1e30f;
        int   i1 = -1,     i2 = -1;
        #pragma unroll
        for (int e = 0; e < 16; e++) {
            float val = v[e];
            if (val > v1)      { v2 = v1; i2 = i1; v1 = val; i1 = e; }
            else if (val > v2) { v2 = val; i2 = e; }
        }

        // softmax over the two kept logits
        float ew  = expf(v2 - v1);
        float inv = 1.0f / (1.0f + ew);
        float w1  = inv;
        float w2  = ew * inv;

        float o[16];
        #pragma unroll
        for (int e = 0; e < 16; e++)
            o[e] = (e == i1) ? w1 : ((e == i2) ? w2 : 0.0f);

        float4* op = (float4*)(out + (size_t)gtok * NE);
        op[0] = make_float4(o[0],  o[1],  o[2],  o[3]);
        op[1] = make_float4(o[4],  o[5],  o[6],  o[7]);
        op[2] = make_float4(o[8],  o[9],  o[10], o[11]);
        op[3] = make_float4(o[12], o[13], o[14], o[15]);
    }
}

extern "C" void kernel_launch(void* const* d_in, const int* in_sizes, int n_in,
                              void* d_out, int out_size)
{
    const float* x     = (const float*)d_in[0];
    const float* noise = (const float*)d_in[1];
    const float* W     = (const float*)d_in[2];
    const float* b     = (const float*)d_in[3];
    float* out = (float*)d_out;

    const int smem_bytes = SMEM_F4_TOTAL * 16;  // 73728
    cudaFuncSetAttribute(gating_moe_kernel,
                         cudaFuncAttributeMaxDynamicSharedMemorySize, smem_bytes);

    gating_moe_kernel<<<TOK / BT, NTHR, smem_bytes>>>(x, noise, W, b, out);
}